// round 1
// baseline (speedup 1.0000x reference)
#include <cuda_runtime.h>
#include <math.h>

// Problem constants
#define BATCH 4
#define SEQ   2048
#define DIMI  768
#define EMB   512
#define HEADS 8
#define HD    64
#define MROWS (BATCH*SEQ)   // 8192

// Scratch (allocation-free: __device__ globals)
__device__ float g_Q[MROWS*EMB];
__device__ float g_K[MROWS*EMB];
__device__ float g_V[MROWS*EMB];
__device__ float g_C[MROWS*EMB];

// ---------------------------------------------------------------------------
// Tiled SGEMM + bias: C[M,N] = A[M,K] @ W[K,N] + bias[N]
// BM=BN=64, BK=16, 256 threads, 4x4 register tile per thread.
// ---------------------------------------------------------------------------
__global__ __launch_bounds__(256)
void gemm_bias(const float* __restrict__ A, const float* __restrict__ W,
               const float* __restrict__ bias, float* __restrict__ C,
               int M, int N, int K)
{
    __shared__ float As[16*68];   // transposed A tile: As[k][m]
    __shared__ float Bs[16*68];   // Bs[k][n]

    const int tid = threadIdx.x;
    const int tx  = tid & 15;     // output col group
    const int ty  = tid >> 4;     // output row group
    const int n0  = blockIdx.x * 64;
    const int m0  = blockIdx.y * 64;

    const int arow = tid >> 2, akq = tid & 3;    // A tile load mapping
    const int bkk  = tid >> 4, bnq = tid & 15;   // B tile load mapping

    float acc[4][4];
    #pragma unroll
    for (int i = 0; i < 4; i++)
        #pragma unroll
        for (int j = 0; j < 4; j++) acc[i][j] = 0.f;

    for (int k0 = 0; k0 < K; k0 += 16) {
        float4 av = *(const float4*)(A + (size_t)(m0 + arow) * K + k0 + akq * 4);
        As[(akq*4 + 0)*68 + arow] = av.x;
        As[(akq*4 + 1)*68 + arow] = av.y;
        As[(akq*4 + 2)*68 + arow] = av.z;
        As[(akq*4 + 3)*68 + arow] = av.w;
        *(float4*)(Bs + bkk*68 + bnq*4) =
            *(const float4*)(W + (size_t)(k0 + bkk) * N + n0 + bnq*4);
        __syncthreads();

        #pragma unroll
        for (int kk = 0; kk < 16; kk++) {
            float4 a = *(const float4*)(As + kk*68 + ty*4);
            float4 b = *(const float4*)(Bs + kk*68 + tx*4);
            float av4[4] = {a.x, a.y, a.z, a.w};
            float bv4[4] = {b.x, b.y, b.z, b.w};
            #pragma unroll
            for (int i = 0; i < 4; i++)
                #pragma unroll
                for (int j = 0; j < 4; j++)
                    acc[i][j] = fmaf(av4[i], bv4[j], acc[i][j]);
        }
        __syncthreads();
    }

    float4 bb = *(const float4*)(bias + n0 + tx*4);
    float bvv[4] = {bb.x, bb.y, bb.z, bb.w};
    #pragma unroll
    for (int i = 0; i < 4; i++) {
        float4 o = make_float4(acc[i][0] + bvv[0], acc[i][1] + bvv[1],
                               acc[i][2] + bvv[2], acc[i][3] + bvv[3]);
        *(float4*)(C + (size_t)(m0 + ty*4 + i) * N + n0 + tx*4) = o;
    }
}

// ---------------------------------------------------------------------------
// FP32 flash attention, one block per (q-tile of 64, batch*head).
// BM=BN=64, Dh=64, 256 threads (16x16 grid, 4x4 per thread).
// Key-column mapping c = tx + 16*j keeps K-tile LDS.128 conflict-free
// (row stride 68 floats -> 8-lane phase covers all 32 banks once).
// ---------------------------------------------------------------------------
__global__ __launch_bounds__(256)
void flash_attn(const float* __restrict__ Qg, const float* __restrict__ Kg,
                const float* __restrict__ Vg, float* __restrict__ Og)
{
    extern __shared__ float sm[];
    float* Qs = sm;                 // [64][64]  row-major (query, dim)
    float* Ks = Qs + 64*64;         // [64][68]  row-major (key, dim), padded
    float* Vs = Ks + 64*68;         // [64][64]  row-major (key, dim)
    float* Pt = Vs + 64*64;         // [64][68]  Pt[key][query], padded

    const int tid = threadIdx.x;
    const int tx  = tid & 15;
    const int ty  = tid >> 4;
    const int q0  = blockIdx.x * 64;
    const int bh  = blockIdx.y;
    const int b   = bh >> 3;
    const int h   = bh & 7;
    const float scale = 0.125f;     // 1/sqrt(64)

    const size_t base = (size_t)b * SEQ * EMB + (size_t)h * HD;

    // Load Q tile once, pre-scaled.
    #pragma unroll
    for (int i = 0; i < 4; i++) {
        int idx = tid + i * 256;
        int r = idx >> 4, dq = idx & 15;
        float4 v = *(const float4*)(Qg + base + (size_t)(q0 + r) * EMB + dq*4);
        v.x *= scale; v.y *= scale; v.z *= scale; v.w *= scale;
        *(float4*)(Qs + r*64 + dq*4) = v;
    }

    float m_i[4], l_i[4], acc[4][4];
    #pragma unroll
    for (int i = 0; i < 4; i++) {
        m_i[i] = -1e30f;
        l_i[i] = 0.f;
        #pragma unroll
        for (int j = 0; j < 4; j++) acc[i][j] = 0.f;
    }

    for (int t = 0; t < SEQ / 64; t++) {
        // Load K, V tiles.
        #pragma unroll
        for (int i = 0; i < 4; i++) {
            int idx = tid + i * 256;
            int r = idx >> 4, dq = idx & 15;
            size_t g = base + (size_t)(t*64 + r) * EMB + dq*4;
            *(float4*)(Ks + r*68 + dq*4) = *(const float4*)(Kg + g);
            *(float4*)(Vs + r*64 + dq*4) = *(const float4*)(Vg + g);
        }
        __syncthreads();

        // Stage 1: S = Q @ K^T (thread owns rows ty*4+i, key cols tx+16*j)
        float s[4][4];
        #pragma unroll
        for (int i = 0; i < 4; i++)
            #pragma unroll
            for (int j = 0; j < 4; j++) s[i][j] = 0.f;

        #pragma unroll 4
        for (int d4 = 0; d4 < 16; d4++) {
            float4 qv[4], kv[4];
            #pragma unroll
            for (int i = 0; i < 4; i++)
                qv[i] = *(const float4*)(Qs + (ty*4 + i)*64 + d4*4);
            #pragma unroll
            for (int j = 0; j < 4; j++)
                kv[j] = *(const float4*)(Ks + (tx + j*16)*68 + d4*4);
            #pragma unroll
            for (int i = 0; i < 4; i++)
                #pragma unroll
                for (int j = 0; j < 4; j++) {
                    s[i][j] = fmaf(qv[i].x, kv[j].x, s[i][j]);
                    s[i][j] = fmaf(qv[i].y, kv[j].y, s[i][j]);
                    s[i][j] = fmaf(qv[i].z, kv[j].z, s[i][j]);
                    s[i][j] = fmaf(qv[i].w, kv[j].w, s[i][j]);
                }
        }

        // Online softmax. Row r=ty*4+i is owned by a contiguous 16-lane group.
        #pragma unroll
        for (int i = 0; i < 4; i++) {
            float rmax = fmaxf(fmaxf(s[i][0], s[i][1]), fmaxf(s[i][2], s[i][3]));
            #pragma unroll
            for (int off = 8; off >= 1; off >>= 1)
                rmax = fmaxf(rmax, __shfl_xor_sync(0xffffffffu, rmax, off));
            float mnew  = fmaxf(m_i[i], rmax);
            float alpha = __expf(m_i[i] - mnew);
            float rsum  = 0.f;
            #pragma unroll
            for (int j = 0; j < 4; j++) {
                float p = __expf(s[i][j] - mnew);
                s[i][j] = p;
                rsum += p;
            }
            #pragma unroll
            for (int off = 8; off >= 1; off >>= 1)
                rsum += __shfl_xor_sync(0xffffffffu, rsum, off);
            l_i[i] = l_i[i] * alpha + rsum;
            m_i[i] = mnew;
            #pragma unroll
            for (int j = 0; j < 4; j++) acc[i][j] *= alpha;
        }

        // Stage P into SMEM transposed: Pt[key][query]
        #pragma unroll
        for (int j = 0; j < 4; j++)
            #pragma unroll
            for (int i = 0; i < 4; i++)
                Pt[(tx + j*16)*68 + ty*4 + i] = s[i][j];
        __syncthreads();

        // Stage 2: O += P @ V  (thread owns rows ty*4+i, out dims tx*4+j)
        #pragma unroll 8
        for (int c = 0; c < 64; c++) {
            float4 pr = *(const float4*)(Pt + c*68 + ty*4);
            float4 vv = *(const float4*)(Vs + c*64 + tx*4);
            float pa[4] = {pr.x, pr.y, pr.z, pr.w};
            float va[4] = {vv.x, vv.y, vv.z, vv.w};
            #pragma unroll
            for (int i = 0; i < 4; i++)
                #pragma unroll
                for (int j = 0; j < 4; j++)
                    acc[i][j] = fmaf(pa[i], va[j], acc[i][j]);
        }
        __syncthreads();
    }

    // Normalize + write context in [B, S, H*Dh] layout.
    #pragma unroll
    for (int i = 0; i < 4; i++) {
        float inv = 1.f / l_i[i];
        float4 o = make_float4(acc[i][0]*inv, acc[i][1]*inv,
                               acc[i][2]*inv, acc[i][3]*inv);
        *(float4*)(Og + base + (size_t)(q0 + ty*4 + i) * EMB + tx*4) = o;
    }
}

// ---------------------------------------------------------------------------
extern "C" void kernel_launch(void* const* d_in, const int* in_sizes, int n_in,
                              void* d_out, int out_size)
{
    const float* q  = (const float*)d_in[0];
    const float* k  = (const float*)d_in[1];
    const float* v  = (const float*)d_in[2];
    const float* wq = (const float*)d_in[3];
    const float* bq = (const float*)d_in[4];
    const float* wk = (const float*)d_in[5];
    const float* bk = (const float*)d_in[6];
    const float* wv = (const float*)d_in[7];
    const float* bv = (const float*)d_in[8];
    const float* wo = (const float*)d_in[9];
    const float* bo = (const float*)d_in[10];
    float* out = (float*)d_out;

    float *Qb, *Kb, *Vb, *Cb;
    cudaGetSymbolAddress((void**)&Qb, g_Q);
    cudaGetSymbolAddress((void**)&Kb, g_K);
    cudaGetSymbolAddress((void**)&Vb, g_V);
    cudaGetSymbolAddress((void**)&Cb, g_C);

    dim3 blk(256);

    // QKV projections: [8192,768] @ [768,512] + bias
    dim3 gp(EMB/64, MROWS/64);
    gemm_bias<<<gp, blk>>>(q, wq, bq, Qb, MROWS, EMB, DIMI);
    gemm_bias<<<gp, blk>>>(k, wk, bk, Kb, MROWS, EMB, DIMI);
    gemm_bias<<<gp, blk>>>(v, wv, bv, Vb, MROWS, EMB, DIMI);

    // Flash attention: grid (S/64, B*H)
    int smem = (64*64 + 64*68 + 64*64 + 64*68) * (int)sizeof(float); // 67584 B
    cudaFuncSetAttribute(flash_attn, cudaFuncAttributeMaxDynamicSharedMemorySize, smem);
    flash_attn<<<dim3(SEQ/64, BATCH*HEADS), blk, smem>>>(Qb, Kb, Vb, Cb);

    // Output projection: [8192,512] @ [512,768] + bias -> d_out
    dim3 go(DIMI/64, MROWS/64);
    gemm_bias<<<go, blk>>>(Cb, wo, bo, out, MROWS, DIMI, EMB);
}

// round 2
// speedup vs baseline: 1.0004x; 1.0004x over previous
#include <cuda_runtime.h>
#include <math.h>

// Problem constants
#define BATCH 4
#define SEQ   2048
#define DIMI  768
#define EMB   512
#define HEADS 8
#define HD    64
#define MROWS (BATCH*SEQ)   // 8192

// Scratch (allocation-free: __device__ globals)
__device__ float g_Q[MROWS*EMB];
__device__ float g_K[MROWS*EMB];
__device__ float g_V[MROWS*EMB];
__device__ float g_C[MROWS*EMB];

// ---------------------------------------------------------------------------
// Tiled SGEMM + bias: C[M,N] = A[M,K] @ W[K,N] + bias[N]
// BM=BN=64, BK=16, 256 threads, 4x4 register tile per thread.
// ---------------------------------------------------------------------------
__global__ __launch_bounds__(256)
void gemm_bias(const float* __restrict__ A, const float* __restrict__ W,
               const float* __restrict__ bias, float* __restrict__ C,
               int M, int N, int K)
{
    __shared__ float As[16*68];   // transposed A tile: As[k][m]
    __shared__ float Bs[16*68];   // Bs[k][n]

    const int tid = threadIdx.x;
    const int tx  = tid & 15;     // output col group
    const int ty  = tid >> 4;     // output row group
    const int n0  = blockIdx.x * 64;
    const int m0  = blockIdx.y * 64;

    const int arow = tid >> 2, akq = tid & 3;    // A tile load mapping
    const int bkk  = tid >> 4, bnq = tid & 15;   // B tile load mapping

    float acc[4][4];
    #pragma unroll
    for (int i = 0; i < 4; i++)
        #pragma unroll
        for (int j = 0; j < 4; j++) acc[i][j] = 0.f;

    for (int k0 = 0; k0 < K; k0 += 16) {
        float4 av = *(const float4*)(A + (size_t)(m0 + arow) * K + k0 + akq * 4);
        As[(akq*4 + 0)*68 + arow] = av.x;
        As[(akq*4 + 1)*68 + arow] = av.y;
        As[(akq*4 + 2)*68 + arow] = av.z;
        As[(akq*4 + 3)*68 + arow] = av.w;
        *(float4*)(Bs + bkk*68 + bnq*4) =
            *(const float4*)(W + (size_t)(k0 + bkk) * N + n0 + bnq*4);
        __syncthreads();

        #pragma unroll
        for (int kk = 0; kk < 16; kk++) {
            float4 a = *(const float4*)(As + kk*68 + ty*4);
            float4 b = *(const float4*)(Bs + kk*68 + tx*4);
            float av4[4] = {a.x, a.y, a.z, a.w};
            float bv4[4] = {b.x, b.y, b.z, b.w};
            #pragma unroll
            for (int i = 0; i < 4; i++)
                #pragma unroll
                for (int j = 0; j < 4; j++)
                    acc[i][j] = fmaf(av4[i], bv4[j], acc[i][j]);
        }
        __syncthreads();
    }

    float4 bb = *(const float4*)(bias + n0 + tx*4);
    float bvv[4] = {bb.x, bb.y, bb.z, bb.w};
    #pragma unroll
    for (int i = 0; i < 4; i++) {
        float4 o = make_float4(acc[i][0] + bvv[0], acc[i][1] + bvv[1],
                               acc[i][2] + bvv[2], acc[i][3] + bvv[3]);
        *(float4*)(C + (size_t)(m0 + ty*4 + i) * N + n0 + tx*4) = o;
    }
}

// ---------------------------------------------------------------------------
// FP32 flash attention, one block per (q-tile of 64, batch*head).
// BM=BN=64, Dh=64, 256 threads (16x16 grid, 4x4 per thread).
// Key-column mapping c = tx + 16*j keeps K-tile LDS.128 conflict-free
// (row stride 68 floats -> 8-lane phase covers all 32 banks once).
// ---------------------------------------------------------------------------
__global__ __launch_bounds__(256)
void flash_attn(const float* __restrict__ Qg, const float* __restrict__ Kg,
                const float* __restrict__ Vg, float* __restrict__ Og)
{
    extern __shared__ float sm[];
    float* Qs = sm;                 // [64][64]  row-major (query, dim)
    float* Ks = Qs + 64*64;         // [64][68]  row-major (key, dim), padded
    float* Vs = Ks + 64*68;         // [64][64]  row-major (key, dim)
    float* Pt = Vs + 64*64;         // [64][68]  Pt[key][query], padded

    const int tid = threadIdx.x;
    const int tx  = tid & 15;
    const int ty  = tid >> 4;
    const int q0  = blockIdx.x * 64;
    const int bh  = blockIdx.y;
    const int b   = bh >> 3;
    const int h   = bh & 7;
    const float scale = 0.125f;     // 1/sqrt(64)

    const size_t base = (size_t)b * SEQ * EMB + (size_t)h * HD;

    // Load Q tile once, pre-scaled.
    #pragma unroll
    for (int i = 0; i < 4; i++) {
        int idx = tid + i * 256;
        int r = idx >> 4, dq = idx & 15;
        float4 v = *(const float4*)(Qg + base + (size_t)(q0 + r) * EMB + dq*4);
        v.x *= scale; v.y *= scale; v.z *= scale; v.w *= scale;
        *(float4*)(Qs + r*64 + dq*4) = v;
    }

    float m_i[4], l_i[4], acc[4][4];
    #pragma unroll
    for (int i = 0; i < 4; i++) {
        m_i[i] = -1e30f;
        l_i[i] = 0.f;
        #pragma unroll
        for (int j = 0; j < 4; j++) acc[i][j] = 0.f;
    }

    for (int t = 0; t < SEQ / 64; t++) {
        // Load K, V tiles.
        #pragma unroll
        for (int i = 0; i < 4; i++) {
            int idx = tid + i * 256;
            int r = idx >> 4, dq = idx & 15;
            size_t g = base + (size_t)(t*64 + r) * EMB + dq*4;
            *(float4*)(Ks + r*68 + dq*4) = *(const float4*)(Kg + g);
            *(float4*)(Vs + r*64 + dq*4) = *(const float4*)(Vg + g);
        }
        __syncthreads();

        // Stage 1: S = Q @ K^T (thread owns rows ty*4+i, key cols tx+16*j)
        float s[4][4];
        #pragma unroll
        for (int i = 0; i < 4; i++)
            #pragma unroll
            for (int j = 0; j < 4; j++) s[i][j] = 0.f;

        #pragma unroll 4
        for (int d4 = 0; d4 < 16; d4++) {
            float4 qv[4], kv[4];
            #pragma unroll
            for (int i = 0; i < 4; i++)
                qv[i] = *(const float4*)(Qs + (ty*4 + i)*64 + d4*4);
            #pragma unroll
            for (int j = 0; j < 4; j++)
                kv[j] = *(const float4*)(Ks + (tx + j*16)*68 + d4*4);
            #pragma unroll
            for (int i = 0; i < 4; i++)
                #pragma unroll
                for (int j = 0; j < 4; j++) {
                    s[i][j] = fmaf(qv[i].x, kv[j].x, s[i][j]);
                    s[i][j] = fmaf(qv[i].y, kv[j].y, s[i][j]);
                    s[i][j] = fmaf(qv[i].z, kv[j].z, s[i][j]);
                    s[i][j] = fmaf(qv[i].w, kv[j].w, s[i][j]);
                }
        }

        // Online softmax. Row r=ty*4+i is owned by a contiguous 16-lane group.
        #pragma unroll
        for (int i = 0; i < 4; i++) {
            float rmax = fmaxf(fmaxf(s[i][0], s[i][1]), fmaxf(s[i][2], s[i][3]));
            #pragma unroll
            for (int off = 8; off >= 1; off >>= 1)
                rmax = fmaxf(rmax, __shfl_xor_sync(0xffffffffu, rmax, off));
            float mnew  = fmaxf(m_i[i], rmax);
            float alpha = __expf(m_i[i] - mnew);
            float rsum  = 0.f;
            #pragma unroll
            for (int j = 0; j < 4; j++) {
                float p = __expf(s[i][j] - mnew);
                s[i][j] = p;
                rsum += p;
            }
            #pragma unroll
            for (int off = 8; off >= 1; off >>= 1)
                rsum += __shfl_xor_sync(0xffffffffu, rsum, off);
            l_i[i] = l_i[i] * alpha + rsum;
            m_i[i] = mnew;
            #pragma unroll
            for (int j = 0; j < 4; j++) acc[i][j] *= alpha;
        }

        // Stage P into SMEM transposed: Pt[key][query]
        #pragma unroll
        for (int j = 0; j < 4; j++)
            #pragma unroll
            for (int i = 0; i < 4; i++)
                Pt[(tx + j*16)*68 + ty*4 + i] = s[i][j];
        __syncthreads();

        // Stage 2: O += P @ V  (thread owns rows ty*4+i, out dims tx*4+j)
        #pragma unroll 8
        for (int c = 0; c < 64; c++) {
            float4 pr = *(const float4*)(Pt + c*68 + ty*4);
            float4 vv = *(const float4*)(Vs + c*64 + tx*4);
            float pa[4] = {pr.x, pr.y, pr.z, pr.w};
            float va[4] = {vv.x, vv.y, vv.z, vv.w};
            #pragma unroll
            for (int i = 0; i < 4; i++)
                #pragma unroll
                for (int j = 0; j < 4; j++)
                    acc[i][j] = fmaf(pa[i], va[j], acc[i][j]);
        }
        __syncthreads();
    }

    // Normalize + write context in [B, S, H*Dh] layout.
    #pragma unroll
    for (int i = 0; i < 4; i++) {
        float inv = 1.f / l_i[i];
        float4 o = make_float4(acc[i][0]*inv, acc[i][1]*inv,
                               acc[i][2]*inv, acc[i][3]*inv);
        *(float4*)(Og + base + (size_t)(q0 + ty*4 + i) * EMB + tx*4) = o;
    }
}

// ---------------------------------------------------------------------------
extern "C" void kernel_launch(void* const* d_in, const int* in_sizes, int n_in,
                              void* d_out, int out_size)
{
    const float* q  = (const float*)d_in[0];
    const float* k  = (const float*)d_in[1];
    const float* v  = (const float*)d_in[2];
    const float* wq = (const float*)d_in[3];
    const float* bq = (const float*)d_in[4];
    const float* wk = (const float*)d_in[5];
    const float* bk = (const float*)d_in[6];
    const float* wv = (const float*)d_in[7];
    const float* bv = (const float*)d_in[8];
    const float* wo = (const float*)d_in[9];
    const float* bo = (const float*)d_in[10];
    float* out = (float*)d_out;

    float *Qb, *Kb, *Vb, *Cb;
    cudaGetSymbolAddress((void**)&Qb, g_Q);
    cudaGetSymbolAddress((void**)&Kb, g_K);
    cudaGetSymbolAddress((void**)&Vb, g_V);
    cudaGetSymbolAddress((void**)&Cb, g_C);

    dim3 blk(256);

    // QKV projections: [8192,768] @ [768,512] + bias
    dim3 gp(EMB/64, MROWS/64);
    gemm_bias<<<gp, blk>>>(q, wq, bq, Qb, MROWS, EMB, DIMI);
    gemm_bias<<<gp, blk>>>(k, wk, bk, Kb, MROWS, EMB, DIMI);
    gemm_bias<<<gp, blk>>>(v, wv, bv, Vb, MROWS, EMB, DIMI);

    // Flash attention: grid (S/64, B*H)
    int smem = (64*64 + 64*68 + 64*64 + 64*68) * (int)sizeof(float); // 67584 B
    cudaFuncSetAttribute(flash_attn, cudaFuncAttributeMaxDynamicSharedMemorySize, smem);
    flash_attn<<<dim3(SEQ/64, BATCH*HEADS), blk, smem>>>(Qb, Kb, Vb, Cb);

    // Output projection: [8192,512] @ [512,768] + bias -> d_out
    dim3 go(DIMI/64, MROWS/64);
    gemm_bias<<<go, blk>>>(Cb, wo, bo, out, MROWS, DIMI, EMB);
}

// round 3
// speedup vs baseline: 2.3652x; 2.3642x over previous
#include <cuda_runtime.h>
#include <math.h>
#include <stdint.h>

// Problem constants
#define BATCH 4
#define SEQ   2048
#define DIMI  768
#define EMB   512
#define HEADS 8
#define HD    64
#define MROWS (BATCH*SEQ)   // 8192

// Scratch (allocation-free: __device__ globals)
__device__ float g_Q[MROWS*EMB];
__device__ float g_K[MROWS*EMB];
__device__ float g_V[MROWS*EMB];
__device__ float g_C[MROWS*EMB];

// ---------------------------------------------------------------------------
// TF32 helpers
// ---------------------------------------------------------------------------
__device__ __forceinline__ uint32_t f2tf(float x) {
    uint32_t r;
    asm("cvt.rna.tf32.f32 %0, %1;" : "=r"(r) : "f"(x));
    return r;
}

// D = A(16x8, tf32) * B(8x8, tf32) + D  (fp32 accum)
__device__ __forceinline__ void mma_tf32(float c[4], const uint32_t a[4],
                                         uint32_t b0, uint32_t b1) {
    asm volatile(
        "mma.sync.aligned.m16n8k8.row.col.f32.tf32.tf32.f32 "
        "{%0,%1,%2,%3}, {%4,%5,%6,%7}, {%8,%9}, {%0,%1,%2,%3};\n"
        : "+f"(c[0]), "+f"(c[1]), "+f"(c[2]), "+f"(c[3])
        : "r"(a[0]), "r"(a[1]), "r"(a[2]), "r"(a[3]), "r"(b0), "r"(b1));
}

// ---------------------------------------------------------------------------
// TF32 tensor-core GEMM + bias: C[M,N] = A[M,K] @ W[K,N] + bias
// BM=128, BN=128, BK=16, 256 threads (8 warps as 2x4), warp tile 64x32.
// ---------------------------------------------------------------------------
#define PADA 20    // A smem [m][k], 16+4 pad: banks (g*20+t) all distinct
#define PADB 136   // B smem [k][n]: banks (t*8+g) distinct per n8 tile

__global__ __launch_bounds__(256, 2)
void gemm_tf32(const float* __restrict__ A, const float* __restrict__ W,
               const float* __restrict__ bias, float* __restrict__ C,
               int M, int N, int K)
{
    __shared__ uint32_t As[128 * PADA];
    __shared__ uint32_t Bs[16 * PADB];

    const int tid  = threadIdx.x;
    const int lane = tid & 31, w = tid >> 5;
    const int g = lane >> 2, t = lane & 3;
    const int wm = (w >> 2) * 64, wn = (w & 3) * 32;
    const int m0 = blockIdx.y * 128, n0 = blockIdx.x * 128;

    float acc[4][4][4];
    #pragma unroll
    for (int mt = 0; mt < 4; mt++)
        #pragma unroll
        for (int nt = 0; nt < 4; nt++)
            #pragma unroll
            for (int c = 0; c < 4; c++) acc[mt][nt][c] = 0.f;

    for (int k0 = 0; k0 < K; k0 += 16) {
        // A tile: 128x16 -> As[m][k]
        #pragma unroll
        for (int it = 0; it < 2; it++) {
            int idx = tid + it * 256;
            int m = idx >> 2, cq = idx & 3;
            float4 v = *(const float4*)(A + (size_t)(m0 + m) * K + k0 + cq * 4);
            uint32_t* p = &As[m * PADA + cq * 4];
            p[0] = f2tf(v.x); p[1] = f2tf(v.y); p[2] = f2tf(v.z); p[3] = f2tf(v.w);
        }
        // B tile: 16x128 -> Bs[k][n]
        #pragma unroll
        for (int it = 0; it < 2; it++) {
            int idx = tid + it * 256;
            int kr = idx >> 5, n4 = idx & 31;
            float4 v = *(const float4*)(W + (size_t)(k0 + kr) * N + n0 + n4 * 4);
            uint32_t* p = &Bs[kr * PADB + n4 * 4];
            p[0] = f2tf(v.x); p[1] = f2tf(v.y); p[2] = f2tf(v.z); p[3] = f2tf(v.w);
        }
        __syncthreads();

        #pragma unroll
        for (int ks = 0; ks < 2; ks++) {
            uint32_t a[4][4], b[4][2];
            #pragma unroll
            for (int mt = 0; mt < 4; mt++) {
                int r = wm + mt * 16;
                a[mt][0] = As[(r + g)     * PADA + ks * 8 + t];
                a[mt][1] = As[(r + g + 8) * PADA + ks * 8 + t];
                a[mt][2] = As[(r + g)     * PADA + ks * 8 + t + 4];
                a[mt][3] = As[(r + g + 8) * PADA + ks * 8 + t + 4];
            }
            #pragma unroll
            for (int nt = 0; nt < 4; nt++) {
                int c = wn + nt * 8 + g;
                b[nt][0] = Bs[(ks * 8 + t)     * PADB + c];
                b[nt][1] = Bs[(ks * 8 + t + 4) * PADB + c];
            }
            #pragma unroll
            for (int mt = 0; mt < 4; mt++)
                #pragma unroll
                for (int nt = 0; nt < 4; nt++)
                    mma_tf32(acc[mt][nt], a[mt], b[nt][0], b[nt][1]);
        }
        __syncthreads();
    }

    // Epilogue: bias + store (float2, rows g and g+8 per m16 tile)
    #pragma unroll
    for (int nt = 0; nt < 4; nt++) {
        int col = n0 + wn + nt * 8 + 2 * t;
        float2 bb = *(const float2*)(bias + col);
        #pragma unroll
        for (int mt = 0; mt < 4; mt++) {
            int r = m0 + wm + mt * 16 + g;
            *(float2*)(C + (size_t)r * N + col) =
                make_float2(acc[mt][nt][0] + bb.x, acc[mt][nt][1] + bb.y);
            *(float2*)(C + (size_t)(r + 8) * N + col) =
                make_float2(acc[mt][nt][2] + bb.x, acc[mt][nt][3] + bb.y);
        }
    }
}

// ---------------------------------------------------------------------------
// TF32 tensor-core flash attention.
// One block = 64 q-rows of one (batch, head). 128 threads = 4 warps,
// warp owns 16 q-rows (one m16 tile). Key tile BN=64, Dh=64.
// S = Q K^T and O += P V both via mma.sync tf32.
// ---------------------------------------------------------------------------
#define QP 68   // Qs [q][d]   : banks g*4+t  all distinct
#define KP 72   // Ks [d][key] : banks t*8+g  distinct per n8
#define VP 72   // Vs [key][d] : banks t*8+g  distinct per n8
#define PP 76   // Ps [q][key] : banks g*12+t all distinct

__global__ __launch_bounds__(128, 2)
void flash_tf32(const float* __restrict__ Qg, const float* __restrict__ Kg,
                const float* __restrict__ Vg, float* __restrict__ Og)
{
    extern __shared__ uint32_t sm[];
    uint32_t* Qs = sm;                // [64][QP]
    uint32_t* Ks = Qs + 64 * QP;      // [64][KP]  (dim, key)
    uint32_t* Vs = Ks + 64 * KP;      // [64][VP]  (key, dim)
    uint32_t* Ps = Vs + 64 * VP;      // [64][PP]  (q, key)

    const int tid  = threadIdx.x;
    const int lane = tid & 31, w = tid >> 5;
    const int g = lane >> 2, t = lane & 3;
    const int wq = w * 16;
    const int q0 = blockIdx.x * 64;
    const int bh = blockIdx.y, b = bh >> 3, h = bh & 7;
    const size_t base = (size_t)b * SEQ * EMB + (size_t)h * HD;

    // Load Q tile once, pre-scaled by 1/sqrt(64), converted to tf32.
    #pragma unroll
    for (int it = 0; it < 8; it++) {
        int idx = tid + it * 128;
        int m = idx >> 4, dq = idx & 15;
        float4 v = *(const float4*)(Qg + base + (size_t)(q0 + m) * EMB + dq * 4);
        uint32_t* p = &Qs[m * QP + dq * 4];
        p[0] = f2tf(v.x * 0.125f); p[1] = f2tf(v.y * 0.125f);
        p[2] = f2tf(v.z * 0.125f); p[3] = f2tf(v.w * 0.125f);
    }

    float m_i[2] = {-1e30f, -1e30f};
    float l_i[2] = {0.f, 0.f};
    float o[8][4];
    #pragma unroll
    for (int nt = 0; nt < 8; nt++)
        #pragma unroll
        for (int c = 0; c < 4; c++) o[nt][c] = 0.f;

    for (int kt = 0; kt < SEQ / 64; kt++) {
        // K tile -> Ks[dim][key] (transposed store, conflict-free: key-contig lanes)
        #pragma unroll
        for (int it = 0; it < 8; it++) {
            int idx = tid + it * 128;
            int key = idx & 63, dq = idx >> 6;
            float4 v = *(const float4*)(Kg + base + (size_t)(kt * 64 + key) * EMB + dq * 4);
            Ks[(dq * 4 + 0) * KP + key] = f2tf(v.x);
            Ks[(dq * 4 + 1) * KP + key] = f2tf(v.y);
            Ks[(dq * 4 + 2) * KP + key] = f2tf(v.z);
            Ks[(dq * 4 + 3) * KP + key] = f2tf(v.w);
        }
        // V tile -> Vs[key][dim] (coalesced)
        #pragma unroll
        for (int it = 0; it < 8; it++) {
            int idx = tid + it * 128;
            int key = idx >> 4, dq = idx & 15;
            float4 v = *(const float4*)(Vg + base + (size_t)(kt * 64 + key) * EMB + dq * 4);
            uint32_t* p = &Vs[key * VP + dq * 4];
            p[0] = f2tf(v.x); p[1] = f2tf(v.y); p[2] = f2tf(v.z); p[3] = f2tf(v.w);
        }
        __syncthreads();

        // S = Q K^T : 8 k-steps x 8 n8-tiles of keys
        float s[8][4];
        #pragma unroll
        for (int nt = 0; nt < 8; nt++)
            #pragma unroll
            for (int c = 0; c < 4; c++) s[nt][c] = 0.f;

        #pragma unroll
        for (int ks = 0; ks < 8; ks++) {
            uint32_t a[4];
            a[0] = Qs[(wq + g)     * QP + ks * 8 + t];
            a[1] = Qs[(wq + g + 8) * QP + ks * 8 + t];
            a[2] = Qs[(wq + g)     * QP + ks * 8 + t + 4];
            a[3] = Qs[(wq + g + 8) * QP + ks * 8 + t + 4];
            #pragma unroll
            for (int nt = 0; nt < 8; nt++) {
                uint32_t b0 = Ks[(ks * 8 + t)     * KP + nt * 8 + g];
                uint32_t b1 = Ks[(ks * 8 + t + 4) * KP + nt * 8 + g];
                mma_tf32(s[nt], a, b0, b1);
            }
        }

        // Online softmax: thread owns rows (wq+g) [c0,c1] and (wq+g+8) [c2,c3];
        // row lives on 4 lanes (same g) -> shfl_xor 1,2.
        #pragma unroll
        for (int hr = 0; hr < 2; hr++) {
            float rmax = -1e30f;
            #pragma unroll
            for (int nt = 0; nt < 8; nt++)
                rmax = fmaxf(rmax, fmaxf(s[nt][2 * hr], s[nt][2 * hr + 1]));
            rmax = fmaxf(rmax, __shfl_xor_sync(0xffffffffu, rmax, 1));
            rmax = fmaxf(rmax, __shfl_xor_sync(0xffffffffu, rmax, 2));
            float mnew  = fmaxf(m_i[hr], rmax);
            float alpha = __expf(m_i[hr] - mnew);
            float rsum = 0.f;
            #pragma unroll
            for (int nt = 0; nt < 8; nt++) {
                float p0 = __expf(s[nt][2 * hr]     - mnew);
                float p1 = __expf(s[nt][2 * hr + 1] - mnew);
                s[nt][2 * hr] = p0; s[nt][2 * hr + 1] = p1;
                rsum += p0 + p1;
            }
            rsum += __shfl_xor_sync(0xffffffffu, rsum, 1);
            rsum += __shfl_xor_sync(0xffffffffu, rsum, 2);
            l_i[hr] = l_i[hr] * alpha + rsum;
            m_i[hr] = mnew;
            #pragma unroll
            for (int nt = 0; nt < 8; nt++) {
                o[nt][2 * hr]     *= alpha;
                o[nt][2 * hr + 1] *= alpha;
            }
        }

        // Stage P (tf32) to SMEM; only warp-local rows -> syncwarp suffices.
        #pragma unroll
        for (int nt = 0; nt < 8; nt++) {
            Ps[(wq + g)     * PP + nt * 8 + 2 * t]     = f2tf(s[nt][0]);
            Ps[(wq + g)     * PP + nt * 8 + 2 * t + 1] = f2tf(s[nt][1]);
            Ps[(wq + g + 8) * PP + nt * 8 + 2 * t]     = f2tf(s[nt][2]);
            Ps[(wq + g + 8) * PP + nt * 8 + 2 * t + 1] = f2tf(s[nt][3]);
        }
        __syncwarp();

        // O += P V : k over 64 keys, n over 64 dims
        #pragma unroll
        for (int ks = 0; ks < 8; ks++) {
            uint32_t a[4];
            a[0] = Ps[(wq + g)     * PP + ks * 8 + t];
            a[1] = Ps[(wq + g + 8) * PP + ks * 8 + t];
            a[2] = Ps[(wq + g)     * PP + ks * 8 + t + 4];
            a[3] = Ps[(wq + g + 8) * PP + ks * 8 + t + 4];
            #pragma unroll
            for (int nt = 0; nt < 8; nt++) {
                uint32_t b0 = Vs[(ks * 8 + t)     * VP + nt * 8 + g];
                uint32_t b1 = Vs[(ks * 8 + t + 4) * VP + nt * 8 + g];
                mma_tf32(o[nt], a, b0, b1);
            }
        }
        __syncthreads();   // protect Ks/Vs before next tile's stores
    }

    // Normalize + write context in [B, S, H*Dh] layout.
    float inv0 = 1.f / l_i[0], inv1 = 1.f / l_i[1];
    #pragma unroll
    for (int nt = 0; nt < 8; nt++) {
        size_t r0 = base + (size_t)(q0 + wq + g) * EMB + nt * 8 + 2 * t;
        *(float2*)(Og + r0) = make_float2(o[nt][0] * inv0, o[nt][1] * inv0);
        size_t r1 = base + (size_t)(q0 + wq + g + 8) * EMB + nt * 8 + 2 * t;
        *(float2*)(Og + r1) = make_float2(o[nt][2] * inv1, o[nt][3] * inv1);
    }
}

// ---------------------------------------------------------------------------
extern "C" void kernel_launch(void* const* d_in, const int* in_sizes, int n_in,
                              void* d_out, int out_size)
{
    const float* q  = (const float*)d_in[0];
    const float* k  = (const float*)d_in[1];
    const float* v  = (const float*)d_in[2];
    const float* wq = (const float*)d_in[3];
    const float* bq = (const float*)d_in[4];
    const float* wk = (const float*)d_in[5];
    const float* bk = (const float*)d_in[6];
    const float* wv = (const float*)d_in[7];
    const float* bv = (const float*)d_in[8];
    const float* wo = (const float*)d_in[9];
    const float* bo = (const float*)d_in[10];
    float* out = (float*)d_out;

    float *Qb, *Kb, *Vb, *Cb;
    cudaGetSymbolAddress((void**)&Qb, g_Q);
    cudaGetSymbolAddress((void**)&Kb, g_K);
    cudaGetSymbolAddress((void**)&Vb, g_V);
    cudaGetSymbolAddress((void**)&Cb, g_C);

    // QKV projections: [8192,768] @ [768,512] + bias
    dim3 gp(EMB / 128, MROWS / 128);
    gemm_tf32<<<gp, 256>>>(q, wq, bq, Qb, MROWS, EMB, DIMI);
    gemm_tf32<<<gp, 256>>>(k, wk, bk, Kb, MROWS, EMB, DIMI);
    gemm_tf32<<<gp, 256>>>(v, wv, bv, Vb, MROWS, EMB, DIMI);

    // Flash attention: grid (S/64, B*H)
    int smem = 64 * (QP + KP + VP + PP) * (int)sizeof(uint32_t);   // 73728 B
    cudaFuncSetAttribute(flash_tf32, cudaFuncAttributeMaxDynamicSharedMemorySize, smem);
    flash_tf32<<<dim3(SEQ / 64, BATCH * HEADS), 128, smem>>>(Qb, Kb, Vb, Cb);

    // Output projection: [8192,512] @ [512,768] + bias -> d_out
    dim3 go(DIMI / 128, MROWS / 128);
    gemm_tf32<<<go, 256>>>(Cb, wo, bo, out, MROWS, DIMI, EMB);
}

// round 4
// speedup vs baseline: 2.6108x; 1.1038x over previous
#include <cuda_runtime.h>
#include <math.h>
#include <stdint.h>

// Problem constants
#define BATCH 4
#define SEQ   2048
#define DIMI  768
#define EMB   512
#define HEADS 8
#define HD    64
#define MROWS (BATCH*SEQ)   // 8192

// Scratch (allocation-free: __device__ globals)
__device__ float g_Q[MROWS*EMB];
__device__ float g_K[MROWS*EMB];
__device__ float g_V[MROWS*EMB];
__device__ float g_C[MROWS*EMB];

// ---------------------------------------------------------------------------
// TF32 helpers
// ---------------------------------------------------------------------------
__device__ __forceinline__ uint32_t f2tf(float x) {
    uint32_t r;
    asm("cvt.rna.tf32.f32 %0, %1;" : "=r"(r) : "f"(x));
    return r;
}

// D = A(16x8, tf32) * B(8x8, tf32) + D  (fp32 accum)
__device__ __forceinline__ void mma_tf32(float c[4], const uint32_t a[4],
                                         uint32_t b0, uint32_t b1) {
    asm volatile(
        "mma.sync.aligned.m16n8k8.row.col.f32.tf32.tf32.f32 "
        "{%0,%1,%2,%3}, {%4,%5,%6,%7}, {%8,%9}, {%0,%1,%2,%3};\n"
        : "+f"(c[0]), "+f"(c[1]), "+f"(c[2]), "+f"(c[3])
        : "r"(a[0]), "r"(a[1]), "r"(a[2]), "r"(a[3]), "r"(b0), "r"(b1));
}

// ---------------------------------------------------------------------------
// TF32 tensor-core GEMM + bias: C[M,N] = A[M,K] @ W[K,N] + bias
// BM=128, BN=128, BK=16, 256 threads (8 warps as 2x4), warp tile 64x32.
// ---------------------------------------------------------------------------
#define PADA 20    // A smem [m][k], 16+4 pad
#define PADB 136   // B smem [k][n]

__global__ __launch_bounds__(256, 2)
void gemm_tf32(const float* __restrict__ A, const float* __restrict__ W,
               const float* __restrict__ bias, float* __restrict__ C,
               int M, int N, int K)
{
    __shared__ uint32_t As[128 * PADA];
    __shared__ uint32_t Bs[16 * PADB];

    const int tid  = threadIdx.x;
    const int lane = tid & 31, w = tid >> 5;
    const int g = lane >> 2, t = lane & 3;
    const int wm = (w >> 2) * 64, wn = (w & 3) * 32;
    const int m0 = blockIdx.y * 128, n0 = blockIdx.x * 128;

    float acc[4][4][4];
    #pragma unroll
    for (int mt = 0; mt < 4; mt++)
        #pragma unroll
        for (int nt = 0; nt < 4; nt++)
            #pragma unroll
            for (int c = 0; c < 4; c++) acc[mt][nt][c] = 0.f;

    for (int k0 = 0; k0 < K; k0 += 16) {
        #pragma unroll
        for (int it = 0; it < 2; it++) {
            int idx = tid + it * 256;
            int m = idx >> 2, cq = idx & 3;
            float4 v = *(const float4*)(A + (size_t)(m0 + m) * K + k0 + cq * 4);
            uint32_t* p = &As[m * PADA + cq * 4];
            p[0] = f2tf(v.x); p[1] = f2tf(v.y); p[2] = f2tf(v.z); p[3] = f2tf(v.w);
        }
        #pragma unroll
        for (int it = 0; it < 2; it++) {
            int idx = tid + it * 256;
            int kr = idx >> 5, n4 = idx & 31;
            float4 v = *(const float4*)(W + (size_t)(k0 + kr) * N + n0 + n4 * 4);
            uint32_t* p = &Bs[kr * PADB + n4 * 4];
            p[0] = f2tf(v.x); p[1] = f2tf(v.y); p[2] = f2tf(v.z); p[3] = f2tf(v.w);
        }
        __syncthreads();

        #pragma unroll
        for (int ks = 0; ks < 2; ks++) {
            uint32_t a[4][4], b[4][2];
            #pragma unroll
            for (int mt = 0; mt < 4; mt++) {
                int r = wm + mt * 16;
                a[mt][0] = As[(r + g)     * PADA + ks * 8 + t];
                a[mt][1] = As[(r + g + 8) * PADA + ks * 8 + t];
                a[mt][2] = As[(r + g)     * PADA + ks * 8 + t + 4];
                a[mt][3] = As[(r + g + 8) * PADA + ks * 8 + t + 4];
            }
            #pragma unroll
            for (int nt = 0; nt < 4; nt++) {
                int c = wn + nt * 8 + g;
                b[nt][0] = Bs[(ks * 8 + t)     * PADB + c];
                b[nt][1] = Bs[(ks * 8 + t + 4) * PADB + c];
            }
            #pragma unroll
            for (int mt = 0; mt < 4; mt++)
                #pragma unroll
                for (int nt = 0; nt < 4; nt++)
                    mma_tf32(acc[mt][nt], a[mt], b[nt][0], b[nt][1]);
        }
        __syncthreads();
    }

    #pragma unroll
    for (int nt = 0; nt < 4; nt++) {
        int col = n0 + wn + nt * 8 + 2 * t;
        float2 bb = *(const float2*)(bias + col);
        #pragma unroll
        for (int mt = 0; mt < 4; mt++) {
            int r = m0 + wm + mt * 16 + g;
            *(float2*)(C + (size_t)r * N + col) =
                make_float2(acc[mt][nt][0] + bb.x, acc[mt][nt][1] + bb.y);
            *(float2*)(C + (size_t)(r + 8) * N + col) =
                make_float2(acc[mt][nt][2] + bb.x, acc[mt][nt][3] + bb.y);
        }
    }
}

// ---------------------------------------------------------------------------
// TF32 flash attention v2: BM=128 q-rows, 4 warps, 32 q-rows (2 m16) per warp.
// K/V tiles in a swizzled class-grouped layout enabling conflict-free LDS.128
// b-fragment loads:
//   word(r,n) = r*64 + (((n&7) ^ 2*(r&3)) + 8*(n>>5))*4 + ((n>>3)&3)
// Lane (g,t) reads float4 at r*64 + ((g ^ 2*(r&3)) + 8h)*4  -> covers
// nt = 4h..4h+3 of B[r][nt*8+g]; per-8-lane-phase slots g^2t are distinct.
// ---------------------------------------------------------------------------
#define QP 68   // Qs [q][d]   : a-load banks 4g+t distinct -> conflict-free
#define PP 76   // Ps [q][key] : a-load banks 12g+t distinct -> conflict-free

__device__ __forceinline__ int kvw(int r, int n) {
    return (r << 6) + ((((n & 7) ^ ((r & 3) << 1)) + ((n >> 5) << 3)) << 2)
                    + ((n >> 3) & 3);
}

__global__ __launch_bounds__(128, 2)
void flash_tf32(const float* __restrict__ Qg, const float* __restrict__ Kg,
                const float* __restrict__ Vg, float* __restrict__ Og)
{
    extern __shared__ uint32_t sm[];
    uint32_t* Qs = sm;                  // [128][QP]
    uint32_t* Ks = Qs + 128 * QP;       // [64*64] swizzled (k-dim rows, key cols)
    uint32_t* Vs = Ks + 64 * 64;        // [64*64] swizzled (key rows, dim cols)
    uint32_t* Ps = Vs + 64 * 64;        // [128][PP]

    const int tid  = threadIdx.x;
    const int lane = tid & 31, w = tid >> 5;
    const int g = lane >> 2, t = lane & 3;
    const int wq = w * 32;              // warp's 32 q-rows
    const int q0 = blockIdx.x * 128;
    const int bh = blockIdx.y, b = bh >> 3, h = bh & 7;
    const size_t base = (size_t)b * SEQ * EMB + (size_t)h * HD;

    // Load Q tile once, pre-scaled by 1/sqrt(64), converted to tf32.
    #pragma unroll
    for (int it = 0; it < 16; it++) {
        int idx = tid + it * 128;
        int m = idx >> 4, dq = idx & 15;
        float4 v = *(const float4*)(Qg + base + (size_t)(q0 + m) * EMB + dq * 4);
        uint32_t* p = &Qs[m * QP + dq * 4];
        p[0] = f2tf(v.x * 0.125f); p[1] = f2tf(v.y * 0.125f);
        p[2] = f2tf(v.z * 0.125f); p[3] = f2tf(v.w * 0.125f);
    }

    float m_i[2][2], l_i[2][2];
    float o[2][8][4];
    #pragma unroll
    for (int mt = 0; mt < 2; mt++) {
        m_i[mt][0] = m_i[mt][1] = -1e30f;
        l_i[mt][0] = l_i[mt][1] = 0.f;
        #pragma unroll
        for (int nt = 0; nt < 8; nt++)
            #pragma unroll
            for (int c = 0; c < 4; c++) o[mt][nt][c] = 0.f;
    }

    for (int kt = 0; kt < SEQ / 64; kt++) {
        // K tile: rows = dim, cols = key. 32 consecutive keys per warp ->
        // conflict-free swizzled STS.
        #pragma unroll
        for (int it = 0; it < 8; it++) {
            int idx = tid + it * 128;
            int key = idx & 63, dq = idx >> 6;
            float4 v = *(const float4*)(Kg + base + (size_t)(kt * 64 + key) * EMB + dq * 4);
            Ks[kvw(dq * 4 + 0, key)] = f2tf(v.x);
            Ks[kvw(dq * 4 + 1, key)] = f2tf(v.y);
            Ks[kvw(dq * 4 + 2, key)] = f2tf(v.z);
            Ks[kvw(dq * 4 + 3, key)] = f2tf(v.w);
        }
        // V tile: rows = key, cols = dim (coalesced gmem; 2-way STS accepted).
        #pragma unroll
        for (int it = 0; it < 8; it++) {
            int idx = tid + it * 128;
            int key = idx >> 4, dq = idx & 15;
            float4 v = *(const float4*)(Vg + base + (size_t)(kt * 64 + key) * EMB + dq * 4);
            Vs[kvw(key, dq * 4 + 0)] = f2tf(v.x);
            Vs[kvw(key, dq * 4 + 1)] = f2tf(v.y);
            Vs[kvw(key, dq * 4 + 2)] = f2tf(v.z);
            Vs[kvw(key, dq * 4 + 3)] = f2tf(v.w);
        }
        __syncthreads();

        // ---- S = Q K^T ----
        float s[2][8][4];
        #pragma unroll
        for (int mt = 0; mt < 2; mt++)
            #pragma unroll
            for (int nt = 0; nt < 8; nt++)
                #pragma unroll
                for (int c = 0; c < 4; c++) s[mt][nt][c] = 0.f;

        #pragma unroll
        for (int ks = 0; ks < 8; ks++) {
            const int r0 = ks * 8 + t, r1 = r0 + 4;   // both have r&3 == t
            const int sw = (g ^ (t << 1)) << 2;
            uint32_t kb0[8], kb1[8];
            {
                uint4 x = *(const uint4*)(Ks + (r0 << 6) + sw);
                kb0[0] = x.x; kb0[1] = x.y; kb0[2] = x.z; kb0[3] = x.w;
                uint4 y = *(const uint4*)(Ks + (r0 << 6) + sw + 32);
                kb0[4] = y.x; kb0[5] = y.y; kb0[6] = y.z; kb0[7] = y.w;
                uint4 z = *(const uint4*)(Ks + (r1 << 6) + sw);
                kb1[0] = z.x; kb1[1] = z.y; kb1[2] = z.z; kb1[3] = z.w;
                uint4 u = *(const uint4*)(Ks + (r1 << 6) + sw + 32);
                kb1[4] = u.x; kb1[5] = u.y; kb1[6] = u.z; kb1[7] = u.w;
            }
            #pragma unroll
            for (int mt = 0; mt < 2; mt++) {
                const int R = wq + mt * 16;
                uint32_t a[4];
                a[0] = Qs[(R + g)     * QP + ks * 8 + t];
                a[1] = Qs[(R + g + 8) * QP + ks * 8 + t];
                a[2] = Qs[(R + g)     * QP + ks * 8 + t + 4];
                a[3] = Qs[(R + g + 8) * QP + ks * 8 + t + 4];
                #pragma unroll
                for (int nt = 0; nt < 8; nt++)
                    mma_tf32(s[mt][nt], a, kb0[nt], kb1[nt]);
            }
        }

        // ---- online softmax (rows live on 4 lanes: shfl_xor 1,2) ----
        #pragma unroll
        for (int mt = 0; mt < 2; mt++) {
            #pragma unroll
            for (int hr = 0; hr < 2; hr++) {
                float rmax = -1e30f;
                #pragma unroll
                for (int nt = 0; nt < 8; nt++)
                    rmax = fmaxf(rmax, fmaxf(s[mt][nt][2 * hr], s[mt][nt][2 * hr + 1]));
                rmax = fmaxf(rmax, __shfl_xor_sync(0xffffffffu, rmax, 1));
                rmax = fmaxf(rmax, __shfl_xor_sync(0xffffffffu, rmax, 2));
                float mnew  = fmaxf(m_i[mt][hr], rmax);
                float alpha = __expf(m_i[mt][hr] - mnew);
                float rsum = 0.f;
                #pragma unroll
                for (int nt = 0; nt < 8; nt++) {
                    float p0 = __expf(s[mt][nt][2 * hr]     - mnew);
                    float p1 = __expf(s[mt][nt][2 * hr + 1] - mnew);
                    s[mt][nt][2 * hr] = p0; s[mt][nt][2 * hr + 1] = p1;
                    rsum += p0 + p1;
                }
                rsum += __shfl_xor_sync(0xffffffffu, rsum, 1);
                rsum += __shfl_xor_sync(0xffffffffu, rsum, 2);
                l_i[mt][hr] = l_i[mt][hr] * alpha + rsum;
                m_i[mt][hr] = mnew;
                #pragma unroll
                for (int nt = 0; nt < 8; nt++) {
                    o[mt][nt][2 * hr]     *= alpha;
                    o[mt][nt][2 * hr + 1] *= alpha;
                }
            }
        }

        // ---- stage P (tf32) to SMEM; warp-local rows only ----
        #pragma unroll
        for (int mt = 0; mt < 2; mt++) {
            const int R = wq + mt * 16;
            #pragma unroll
            for (int nt = 0; nt < 8; nt++) {
                *(uint2*)&Ps[(R + g) * PP + nt * 8 + 2 * t] =
                    make_uint2(f2tf(s[mt][nt][0]), f2tf(s[mt][nt][1]));
                *(uint2*)&Ps[(R + g + 8) * PP + nt * 8 + 2 * t] =
                    make_uint2(f2tf(s[mt][nt][2]), f2tf(s[mt][nt][3]));
            }
        }
        __syncwarp();

        // ---- O += P V ----
        #pragma unroll
        for (int ks = 0; ks < 8; ks++) {
            const int r0 = ks * 8 + t, r1 = r0 + 4;
            const int sw = (g ^ (t << 1)) << 2;
            uint32_t vb0[8], vb1[8];
            {
                uint4 x = *(const uint4*)(Vs + (r0 << 6) + sw);
                vb0[0] = x.x; vb0[1] = x.y; vb0[2] = x.z; vb0[3] = x.w;
                uint4 y = *(const uint4*)(Vs + (r0 << 6) + sw + 32);
                vb0[4] = y.x; vb0[5] = y.y; vb0[6] = y.z; vb0[7] = y.w;
                uint4 z = *(const uint4*)(Vs + (r1 << 6) + sw);
                vb1[0] = z.x; vb1[1] = z.y; vb1[2] = z.z; vb1[3] = z.w;
                uint4 u = *(const uint4*)(Vs + (r1 << 6) + sw + 32);
                vb1[4] = u.x; vb1[5] = u.y; vb1[6] = u.z; vb1[7] = u.w;
            }
            #pragma unroll
            for (int mt = 0; mt < 2; mt++) {
                const int R = wq + mt * 16;
                uint32_t a[4];
                a[0] = Ps[(R + g)     * PP + ks * 8 + t];
                a[1] = Ps[(R + g + 8) * PP + ks * 8 + t];
                a[2] = Ps[(R + g)     * PP + ks * 8 + t + 4];
                a[3] = Ps[(R + g + 8) * PP + ks * 8 + t + 4];
                #pragma unroll
                for (int nt = 0; nt < 8; nt++)
                    mma_tf32(o[mt][nt], a, vb0[nt], vb1[nt]);
            }
        }
        __syncthreads();   // protect Ks/Vs before next tile's stores
    }

    // Normalize + write context in [B, S, H*Dh] layout.
    #pragma unroll
    for (int mt = 0; mt < 2; mt++) {
        float inv0 = 1.f / l_i[mt][0], inv1 = 1.f / l_i[mt][1];
        const int R = q0 + wq + mt * 16;
        #pragma unroll
        for (int nt = 0; nt < 8; nt++) {
            size_t r0 = base + (size_t)(R + g) * EMB + nt * 8 + 2 * t;
            *(float2*)(Og + r0) = make_float2(o[mt][nt][0] * inv0, o[mt][nt][1] * inv0);
            size_t r1 = base + (size_t)(R + g + 8) * EMB + nt * 8 + 2 * t;
            *(float2*)(Og + r1) = make_float2(o[mt][nt][2] * inv1, o[mt][nt][3] * inv1);
        }
    }
}

// ---------------------------------------------------------------------------
extern "C" void kernel_launch(void* const* d_in, const int* in_sizes, int n_in,
                              void* d_out, int out_size)
{
    const float* q  = (const float*)d_in[0];
    const float* k  = (const float*)d_in[1];
    const float* v  = (const float*)d_in[2];
    const float* wq = (const float*)d_in[3];
    const float* bq = (const float*)d_in[4];
    const float* wk = (const float*)d_in[5];
    const float* bk = (const float*)d_in[6];
    const float* wv = (const float*)d_in[7];
    const float* bv = (const float*)d_in[8];
    const float* wo = (const float*)d_in[9];
    const float* bo = (const float*)d_in[10];
    float* out = (float*)d_out;

    float *Qb, *Kb, *Vb, *Cb;
    cudaGetSymbolAddress((void**)&Qb, g_Q);
    cudaGetSymbolAddress((void**)&Kb, g_K);
    cudaGetSymbolAddress((void**)&Vb, g_V);
    cudaGetSymbolAddress((void**)&Cb, g_C);

    // QKV projections: [8192,768] @ [768,512] + bias
    dim3 gp(EMB / 128, MROWS / 128);
    gemm_tf32<<<gp, 256>>>(q, wq, bq, Qb, MROWS, EMB, DIMI);
    gemm_tf32<<<gp, 256>>>(k, wk, bk, Kb, MROWS, EMB, DIMI);
    gemm_tf32<<<gp, 256>>>(v, wv, bv, Vb, MROWS, EMB, DIMI);

    // Flash attention: grid (S/128, B*H)
    int smem = (128 * QP + 64 * 64 * 2 + 128 * PP) * (int)sizeof(uint32_t); // 106496
    cudaFuncSetAttribute(flash_tf32, cudaFuncAttributeMaxDynamicSharedMemorySize, smem);
    flash_tf32<<<dim3(SEQ / 128, BATCH * HEADS), 128, smem>>>(Qb, Kb, Vb, Cb);

    // Output projection: [8192,512] @ [512,768] + bias -> d_out
    dim3 go(DIMI / 128, MROWS / 128);
    gemm_tf32<<<go, 256>>>(Cb, wo, bo, out, MROWS, DIMI, EMB);
}

// round 5
// speedup vs baseline: 2.6252x; 1.0055x over previous
#include <cuda_runtime.h>
#include <math.h>
#include <stdint.h>

// Problem constants
#define BATCH 4
#define SEQ   2048
#define DIMI  768
#define EMB   512
#define HEADS 8
#define HD    64
#define MROWS (BATCH*SEQ)   // 8192

// Scratch (allocation-free: __device__ globals)
__device__ float g_Q[MROWS*EMB];
__device__ float g_K[MROWS*EMB];
__device__ float g_V[MROWS*EMB];
__device__ float g_C[MROWS*EMB];

// ---------------------------------------------------------------------------
// TF32 helpers
// ---------------------------------------------------------------------------
__device__ __forceinline__ uint32_t f2tf(float x) {
    uint32_t r;
    asm("cvt.rna.tf32.f32 %0, %1;" : "=r"(r) : "f"(x));
    return r;
}

__device__ __forceinline__ float ex2(float x) {
    float y;
    asm("ex2.approx.f32 %0, %1;" : "=f"(y) : "f"(x));
    return y;
}

// D = A(16x8, tf32) * B(8x8, tf32) + D  (fp32 accum)
__device__ __forceinline__ void mma_tf32(float c[4], const uint32_t a[4],
                                         uint32_t b0, uint32_t b1) {
    asm volatile(
        "mma.sync.aligned.m16n8k8.row.col.f32.tf32.tf32.f32 "
        "{%0,%1,%2,%3}, {%4,%5,%6,%7}, {%8,%9}, {%0,%1,%2,%3};\n"
        : "+f"(c[0]), "+f"(c[1]), "+f"(c[2]), "+f"(c[3])
        : "r"(a[0]), "r"(a[1]), "r"(a[2]), "r"(a[3]), "r"(b0), "r"(b1));
}

// ---------------------------------------------------------------------------
// TF32 tensor-core GEMM + bias (unchanged from round 4 — control group)
// ---------------------------------------------------------------------------
#define PADA 20
#define PADB 136

__global__ __launch_bounds__(256, 2)
void gemm_tf32(const float* __restrict__ A, const float* __restrict__ W,
               const float* __restrict__ bias, float* __restrict__ C,
               int M, int N, int K)
{
    __shared__ uint32_t As[128 * PADA];
    __shared__ uint32_t Bs[16 * PADB];

    const int tid  = threadIdx.x;
    const int lane = tid & 31, w = tid >> 5;
    const int g = lane >> 2, t = lane & 3;
    const int wm = (w >> 2) * 64, wn = (w & 3) * 32;
    const int m0 = blockIdx.y * 128, n0 = blockIdx.x * 128;

    float acc[4][4][4];
    #pragma unroll
    for (int mt = 0; mt < 4; mt++)
        #pragma unroll
        for (int nt = 0; nt < 4; nt++)
            #pragma unroll
            for (int c = 0; c < 4; c++) acc[mt][nt][c] = 0.f;

    for (int k0 = 0; k0 < K; k0 += 16) {
        #pragma unroll
        for (int it = 0; it < 2; it++) {
            int idx = tid + it * 256;
            int m = idx >> 2, cq = idx & 3;
            float4 v = *(const float4*)(A + (size_t)(m0 + m) * K + k0 + cq * 4);
            uint32_t* p = &As[m * PADA + cq * 4];
            p[0] = f2tf(v.x); p[1] = f2tf(v.y); p[2] = f2tf(v.z); p[3] = f2tf(v.w);
        }
        #pragma unroll
        for (int it = 0; it < 2; it++) {
            int idx = tid + it * 256;
            int kr = idx >> 5, n4 = idx & 31;
            float4 v = *(const float4*)(W + (size_t)(k0 + kr) * N + n0 + n4 * 4);
            uint32_t* p = &Bs[kr * PADB + n4 * 4];
            p[0] = f2tf(v.x); p[1] = f2tf(v.y); p[2] = f2tf(v.z); p[3] = f2tf(v.w);
        }
        __syncthreads();

        #pragma unroll
        for (int ks = 0; ks < 2; ks++) {
            uint32_t a[4][4], b[4][2];
            #pragma unroll
            for (int mt = 0; mt < 4; mt++) {
                int r = wm + mt * 16;
                a[mt][0] = As[(r + g)     * PADA + ks * 8 + t];
                a[mt][1] = As[(r + g + 8) * PADA + ks * 8 + t];
                a[mt][2] = As[(r + g)     * PADA + ks * 8 + t + 4];
                a[mt][3] = As[(r + g + 8) * PADA + ks * 8 + t + 4];
            }
            #pragma unroll
            for (int nt = 0; nt < 4; nt++) {
                int c = wn + nt * 8 + g;
                b[nt][0] = Bs[(ks * 8 + t)     * PADB + c];
                b[nt][1] = Bs[(ks * 8 + t + 4) * PADB + c];
            }
            #pragma unroll
            for (int mt = 0; mt < 4; mt++)
                #pragma unroll
                for (int nt = 0; nt < 4; nt++)
                    mma_tf32(acc[mt][nt], a[mt], b[nt][0], b[nt][1]);
        }
        __syncthreads();
    }

    #pragma unroll
    for (int nt = 0; nt < 4; nt++) {
        int col = n0 + wn + nt * 8 + 2 * t;
        float2 bb = *(const float2*)(bias + col);
        #pragma unroll
        for (int mt = 0; mt < 4; mt++) {
            int r = m0 + wm + mt * 16 + g;
            *(float2*)(C + (size_t)r * N + col) =
                make_float2(acc[mt][nt][0] + bb.x, acc[mt][nt][1] + bb.y);
            *(float2*)(C + (size_t)(r + 8) * N + col) =
                make_float2(acc[mt][nt][2] + bb.x, acc[mt][nt][3] + bb.y);
        }
    }
}

// ---------------------------------------------------------------------------
// TF32 flash attention v3: BM=128, 4 warps, 32 q-rows (2 m16) per warp.
//  - P transpose via warp shuffles (no P SMEM round trip)
//  - register-prefetch pipeline: K(t+1) loads overlap S(t), V(t+1) overlaps PV(t)
//  - exp2-domain softmax (log2e folded into Q scale)
// K/V in swizzled class-grouped SMEM:
//   word(r,n) = r*64 + (((n&7) ^ 2*(r&3)) + 8*(n>>5))*4 + ((n>>3)&3)
// ---------------------------------------------------------------------------
#define QP 68   // Qs [q][d]: a-load banks 4g+t distinct -> conflict-free

__device__ __forceinline__ int kvw(int r, int n) {
    return (r << 6) + ((((n & 7) ^ ((r & 3) << 1)) + ((n >> 5) << 3)) << 2)
                    + ((n >> 3) & 3);
}

__global__ __launch_bounds__(128, 2)
void flash_tf32(const float* __restrict__ Qg, const float* __restrict__ Kg,
                const float* __restrict__ Vg, float* __restrict__ Og)
{
    extern __shared__ uint32_t smx[];
    uint32_t* Qs = smx;                 // [128][QP]
    uint32_t* Ks = Qs + 128 * QP;       // [64*64] swizzled (dim rows, key cols)
    uint32_t* Vs = Ks + 64 * 64;        // [64*64] swizzled (key rows, dim cols)

    const int tid  = threadIdx.x;
    const int lane = tid & 31, w = tid >> 5;
    const int g = lane >> 2, t = lane & 3;
    const int wq = w * 32;
    const int q0 = blockIdx.x * 128;
    const int bh = blockIdx.y, b = bh >> 3, h = bh & 7;
    const size_t base = (size_t)b * SEQ * EMB + (size_t)h * HD;
    const float qscale = 0.125f * 1.44269504089f;   // 1/sqrt(64) * log2(e)

    // K loader mapping: key = idx&63, dq = idx>>6 (transposed store)
    // V loader mapping: key = idx>>4, dq = idx&15 (coalesced)
    float4 kr[8], vr[8];

    // Load Q tile once (pre-scaled into exp2 domain, tf32).
    #pragma unroll
    for (int it = 0; it < 16; it++) {
        int idx = tid + it * 128;
        int m = idx >> 4, dq = idx & 15;
        float4 v = *(const float4*)(Qg + base + (size_t)(q0 + m) * EMB + dq * 4);
        uint32_t* p = &Qs[m * QP + dq * 4];
        p[0] = f2tf(v.x * qscale); p[1] = f2tf(v.y * qscale);
        p[2] = f2tf(v.z * qscale); p[3] = f2tf(v.w * qscale);
    }

    // Preload tile 0.
    #pragma unroll
    for (int it = 0; it < 8; it++) {
        int idx = tid + it * 128;
        int key = idx & 63, dq = idx >> 6;
        kr[it] = *(const float4*)(Kg + base + (size_t)key * EMB + dq * 4);
    }
    #pragma unroll
    for (int it = 0; it < 8; it++) {
        int idx = tid + it * 128;
        int key = idx & 63, dq = idx >> 6;
        Ks[kvw(dq * 4 + 0, key)] = f2tf(kr[it].x);
        Ks[kvw(dq * 4 + 1, key)] = f2tf(kr[it].y);
        Ks[kvw(dq * 4 + 2, key)] = f2tf(kr[it].z);
        Ks[kvw(dq * 4 + 3, key)] = f2tf(kr[it].w);
    }
    #pragma unroll
    for (int it = 0; it < 8; it++) {
        int idx = tid + it * 128;
        int key = idx >> 4, dq = idx & 15;
        vr[it] = *(const float4*)(Vg + base + (size_t)key * EMB + dq * 4);
    }
    #pragma unroll
    for (int it = 0; it < 8; it++) {
        int idx = tid + it * 128;
        int key = idx >> 4, dq = idx & 15;
        Vs[kvw(key, dq * 4 + 0)] = f2tf(vr[it].x);
        Vs[kvw(key, dq * 4 + 1)] = f2tf(vr[it].y);
        Vs[kvw(key, dq * 4 + 2)] = f2tf(vr[it].z);
        Vs[kvw(key, dq * 4 + 3)] = f2tf(vr[it].w);
    }
    __syncthreads();

    float m_i[2][2], l_i[2][2];
    float o[2][8][4];
    #pragma unroll
    for (int mt = 0; mt < 2; mt++) {
        m_i[mt][0] = m_i[mt][1] = -1e30f;
        l_i[mt][0] = l_i[mt][1] = 0.f;
        #pragma unroll
        for (int nt = 0; nt < 8; nt++)
            #pragma unroll
            for (int c = 0; c < 4; c++) o[mt][nt][c] = 0.f;
    }

    for (int kt = 0; kt < SEQ / 64; kt++) {
        const bool pf = (kt + 1 < SEQ / 64);
        // Prefetch K(kt+1) into registers (overlaps S-compute).
        if (pf) {
            const size_t kb = base + (size_t)((kt + 1) * 64) * EMB;
            #pragma unroll
            for (int it = 0; it < 8; it++) {
                int idx = tid + it * 128;
                int key = idx & 63, dq = idx >> 6;
                kr[it] = *(const float4*)(Kg + kb + (size_t)key * EMB + dq * 4);
            }
        }

        // ---- S = Q K^T ----
        float s[2][8][4];
        #pragma unroll
        for (int mt = 0; mt < 2; mt++)
            #pragma unroll
            for (int nt = 0; nt < 8; nt++)
                #pragma unroll
                for (int c = 0; c < 4; c++) s[mt][nt][c] = 0.f;

        #pragma unroll
        for (int ks = 0; ks < 8; ks++) {
            const int r0 = ks * 8 + t, r1 = r0 + 4;
            const int sw = (g ^ (t << 1)) << 2;
            uint32_t kb0[8], kb1[8];
            {
                uint4 x = *(const uint4*)(Ks + (r0 << 6) + sw);
                kb0[0] = x.x; kb0[1] = x.y; kb0[2] = x.z; kb0[3] = x.w;
                uint4 y = *(const uint4*)(Ks + (r0 << 6) + sw + 32);
                kb0[4] = y.x; kb0[5] = y.y; kb0[6] = y.z; kb0[7] = y.w;
                uint4 z = *(const uint4*)(Ks + (r1 << 6) + sw);
                kb1[0] = z.x; kb1[1] = z.y; kb1[2] = z.z; kb1[3] = z.w;
                uint4 u = *(const uint4*)(Ks + (r1 << 6) + sw + 32);
                kb1[4] = u.x; kb1[5] = u.y; kb1[6] = u.z; kb1[7] = u.w;
            }
            #pragma unroll
            for (int mt = 0; mt < 2; mt++) {
                const int R = wq + mt * 16;
                uint32_t a[4];
                a[0] = Qs[(R + g)     * QP + ks * 8 + t];
                a[1] = Qs[(R + g + 8) * QP + ks * 8 + t];
                a[2] = Qs[(R + g)     * QP + ks * 8 + t + 4];
                a[3] = Qs[(R + g + 8) * QP + ks * 8 + t + 4];
                #pragma unroll
                for (int nt = 0; nt < 8; nt++)
                    mma_tf32(s[mt][nt], a, kb0[nt], kb1[nt]);
            }
        }

        // ---- online softmax (exp2 domain); converts s in-place to tf32 bits ----
        #pragma unroll
        for (int mt = 0; mt < 2; mt++) {
            #pragma unroll
            for (int hr = 0; hr < 2; hr++) {
                float rmax = -1e30f;
                #pragma unroll
                for (int nt = 0; nt < 8; nt++)
                    rmax = fmaxf(rmax, fmaxf(s[mt][nt][2 * hr], s[mt][nt][2 * hr + 1]));
                rmax = fmaxf(rmax, __shfl_xor_sync(0xffffffffu, rmax, 1));
                rmax = fmaxf(rmax, __shfl_xor_sync(0xffffffffu, rmax, 2));
                float mnew  = fmaxf(m_i[mt][hr], rmax);
                float alpha = ex2(m_i[mt][hr] - mnew);
                float rsum = 0.f;
                #pragma unroll
                for (int nt = 0; nt < 8; nt++) {
                    float p0 = ex2(s[mt][nt][2 * hr]     - mnew);
                    float p1 = ex2(s[mt][nt][2 * hr + 1] - mnew);
                    rsum += p0 + p1;
                    s[mt][nt][2 * hr]     = __uint_as_float(f2tf(p0));
                    s[mt][nt][2 * hr + 1] = __uint_as_float(f2tf(p1));
                }
                rsum += __shfl_xor_sync(0xffffffffu, rsum, 1);
                rsum += __shfl_xor_sync(0xffffffffu, rsum, 2);
                l_i[mt][hr] = l_i[mt][hr] * alpha + rsum;
                m_i[mt][hr] = mnew;
                #pragma unroll
                for (int nt = 0; nt < 8; nt++) {
                    o[mt][nt][2 * hr]     *= alpha;
                    o[mt][nt][2 * hr + 1] *= alpha;
                }
            }
        }

        __syncthreads();   // all warps done reading Ks(kt)

        // Store prefetched K(kt+1); prefetch V(kt+1) (overlaps PV).
        if (pf) {
            #pragma unroll
            for (int it = 0; it < 8; it++) {
                int idx = tid + it * 128;
                int key = idx & 63, dq = idx >> 6;
                Ks[kvw(dq * 4 + 0, key)] = f2tf(kr[it].x);
                Ks[kvw(dq * 4 + 1, key)] = f2tf(kr[it].y);
                Ks[kvw(dq * 4 + 2, key)] = f2tf(kr[it].z);
                Ks[kvw(dq * 4 + 3, key)] = f2tf(kr[it].w);
            }
            const size_t vb = base + (size_t)((kt + 1) * 64) * EMB;
            #pragma unroll
            for (int it = 0; it < 8; it++) {
                int idx = tid + it * 128;
                int key = idx >> 4, dq = idx & 15;
                vr[it] = *(const float4*)(Vg + vb + (size_t)key * EMB + dq * 4);
            }
        }

        // ---- O += P V (P a-frags via warp shuffle of s) ----
        const int srcA = (lane & ~3) | (t >> 1);   // 4g + t/2
        const int srcB = srcA + 2;
        const bool odd = (t & 1);
        #pragma unroll
        for (int ks = 0; ks < 8; ks++) {
            const int r0 = ks * 8 + t, r1 = r0 + 4;
            const int sw = (g ^ (t << 1)) << 2;
            uint32_t vb0[8], vb1[8];
            {
                uint4 x = *(const uint4*)(Vs + (r0 << 6) + sw);
                vb0[0] = x.x; vb0[1] = x.y; vb0[2] = x.z; vb0[3] = x.w;
                uint4 y = *(const uint4*)(Vs + (r0 << 6) + sw + 32);
                vb0[4] = y.x; vb0[5] = y.y; vb0[6] = y.z; vb0[7] = y.w;
                uint4 z = *(const uint4*)(Vs + (r1 << 6) + sw);
                vb1[0] = z.x; vb1[1] = z.y; vb1[2] = z.z; vb1[3] = z.w;
                uint4 u = *(const uint4*)(Vs + (r1 << 6) + sw + 32);
                vb1[4] = u.x; vb1[5] = u.y; vb1[6] = u.z; vb1[7] = u.w;
            }
            #pragma unroll
            for (int mt = 0; mt < 2; mt++) {
                float w0 = __shfl_sync(0xffffffffu, s[mt][ks][0], srcA);
                float w1 = __shfl_sync(0xffffffffu, s[mt][ks][1], srcA);
                float w2 = __shfl_sync(0xffffffffu, s[mt][ks][2], srcA);
                float w3 = __shfl_sync(0xffffffffu, s[mt][ks][3], srcA);
                float x0 = __shfl_sync(0xffffffffu, s[mt][ks][0], srcB);
                float x1 = __shfl_sync(0xffffffffu, s[mt][ks][1], srcB);
                float x2 = __shfl_sync(0xffffffffu, s[mt][ks][2], srcB);
                float x3 = __shfl_sync(0xffffffffu, s[mt][ks][3], srcB);
                uint32_t a[4];
                a[0] = __float_as_uint(odd ? w1 : w0);
                a[1] = __float_as_uint(odd ? w3 : w2);
                a[2] = __float_as_uint(odd ? x1 : x0);
                a[3] = __float_as_uint(odd ? x3 : x2);
                #pragma unroll
                for (int nt = 0; nt < 8; nt++)
                    mma_tf32(o[mt][nt], a, vb0[nt], vb1[nt]);
            }
        }

        __syncthreads();   // all warps done reading Vs(kt)

        if (pf) {
            #pragma unroll
            for (int it = 0; it < 8; it++) {
                int idx = tid + it * 128;
                int key = idx >> 4, dq = idx & 15;
                Vs[kvw(key, dq * 4 + 0)] = f2tf(vr[it].x);
                Vs[kvw(key, dq * 4 + 1)] = f2tf(vr[it].y);
                Vs[kvw(key, dq * 4 + 2)] = f2tf(vr[it].z);
                Vs[kvw(key, dq * 4 + 3)] = f2tf(vr[it].w);
            }
        }
        // V(kt+1) STS is ordered before PV(kt+1) by the next iteration's
        // first __syncthreads(); K(kt+1) STS before S(kt+1) by the second.
    }

    // Normalize + write context in [B, S, H*Dh] layout.
    #pragma unroll
    for (int mt = 0; mt < 2; mt++) {
        float inv0 = __fdividef(1.f, l_i[mt][0]);
        float inv1 = __fdividef(1.f, l_i[mt][1]);
        const int R = q0 + wq + mt * 16;
        #pragma unroll
        for (int nt = 0; nt < 8; nt++) {
            size_t r0 = base + (size_t)(R + g) * EMB + nt * 8 + 2 * t;
            *(float2*)(Og + r0) = make_float2(o[mt][nt][0] * inv0, o[mt][nt][1] * inv0);
            size_t r1 = base + (size_t)(R + g + 8) * EMB + nt * 8 + 2 * t;
            *(float2*)(Og + r1) = make_float2(o[mt][nt][2] * inv1, o[mt][nt][3] * inv1);
        }
    }
}

// ---------------------------------------------------------------------------
extern "C" void kernel_launch(void* const* d_in, const int* in_sizes, int n_in,
                              void* d_out, int out_size)
{
    const float* q  = (const float*)d_in[0];
    const float* k  = (const float*)d_in[1];
    const float* v  = (const float*)d_in[2];
    const float* wq = (const float*)d_in[3];
    const float* bq = (const float*)d_in[4];
    const float* wk = (const float*)d_in[5];
    const float* bk = (const float*)d_in[6];
    const float* wv = (const float*)d_in[7];
    const float* bv = (const float*)d_in[8];
    const float* wo = (const float*)d_in[9];
    const float* bo = (const float*)d_in[10];
    float* out = (float*)d_out;

    float *Qb, *Kb, *Vb, *Cb;
    cudaGetSymbolAddress((void**)&Qb, g_Q);
    cudaGetSymbolAddress((void**)&Kb, g_K);
    cudaGetSymbolAddress((void**)&Vb, g_V);
    cudaGetSymbolAddress((void**)&Cb, g_C);

    // QKV projections: [8192,768] @ [768,512] + bias
    dim3 gp(EMB / 128, MROWS / 128);
    gemm_tf32<<<gp, 256>>>(q, wq, bq, Qb, MROWS, EMB, DIMI);
    gemm_tf32<<<gp, 256>>>(k, wk, bk, Kb, MROWS, EMB, DIMI);
    gemm_tf32<<<gp, 256>>>(v, wv, bv, Vb, MROWS, EMB, DIMI);

    // Flash attention: grid (S/128, B*H)
    int smem = (128 * QP + 64 * 64 * 2) * (int)sizeof(uint32_t);  // 67584 B
    cudaFuncSetAttribute(flash_tf32, cudaFuncAttributeMaxDynamicSharedMemorySize, smem);
    flash_tf32<<<dim3(SEQ / 128, BATCH * HEADS), 128, smem>>>(Qb, Kb, Vb, Cb);

    // Output projection: [8192,512] @ [512,768] + bias -> d_out
    dim3 go(DIMI / 128, MROWS / 128);
    gemm_tf32<<<go, 256>>>(Cb, wo, bo, out, MROWS, DIMI, EMB);
}